// round 1
// baseline (speedup 1.0000x reference)
#include <cuda_runtime.h>

#define BB 2
#define SS 2048
#define HH 1024
#define NHH 16
#define HDD 64
#define MM (BB*SS)   // 4096
#define LN_EPS 1e-5f

// Scratch (allocation-free rule: __device__ globals)
__device__ float g_xn[MM*HH];
__device__ float g_q [MM*HH];
__device__ float g_k [MM*HH];
__device__ float g_v [MM*HH];
__device__ float g_ao[MM*HH];

// ---------------------------------------------------------------------------
// LayerNorm: one block per row, 256 threads, float4
// ---------------------------------------------------------------------------
__global__ __launch_bounds__(256) void ln_kernel(const float* __restrict__ x,
                                                 const float* __restrict__ gamma,
                                                 const float* __restrict__ beta) {
    int row = blockIdx.x;
    int t = threadIdx.x;
    const float4* xr = reinterpret_cast<const float4*>(x + (size_t)row * HH);
    float4 a = xr[t];
    float s  = a.x + a.y + a.z + a.w;
    float sq = a.x*a.x + a.y*a.y + a.z*a.z + a.w*a.w;
    #pragma unroll
    for (int o = 16; o > 0; o >>= 1) {
        s  += __shfl_xor_sync(0xffffffff, s,  o);
        sq += __shfl_xor_sync(0xffffffff, sq, o);
    }
    __shared__ float red0[8], red1[8];
    int wid = t >> 5, lid = t & 31;
    if (lid == 0) { red0[wid] = s; red1[wid] = sq; }
    __syncthreads();
    float fs = 0.f, fq = 0.f;
    #pragma unroll
    for (int i = 0; i < 8; i++) { fs += red0[i]; fq += red1[i]; }
    float mu   = fs * (1.0f / HH);
    float var  = fq * (1.0f / HH) - mu * mu;
    float rstd = rsqrtf(var + LN_EPS);
    float4 gg = reinterpret_cast<const float4*>(gamma)[t];
    float4 bb = reinterpret_cast<const float4*>(beta )[t];
    float4 o;
    o.x = (a.x - mu) * rstd * gg.x + bb.x;
    o.y = (a.y - mu) * rstd * gg.y + bb.y;
    o.z = (a.z - mu) * rstd * gg.z + bb.z;
    o.w = (a.w - mu) * rstd * gg.w + bb.w;
    reinterpret_cast<float4*>(g_xn + (size_t)row * HH)[t] = o;
}

// ---------------------------------------------------------------------------
// GEMM NT: C[m][n] = sum_k A[m][k] * W[n][k]   (A: MMxHH, W: HHxHH row-major)
// 64x64 block tile, BK=32, 256 threads, 4x4 per thread.
// EPI: add bias[n] + resid[m][n] (for output projection).
// ---------------------------------------------------------------------------
template<bool EPI>
__global__ __launch_bounds__(256) void gemm_nt(const float* __restrict__ A,
                                               const float* __restrict__ W,
                                               float* __restrict__ C,
                                               const float* __restrict__ bias,
                                               const float* __restrict__ resid) {
    const int BK = 32;
    __shared__ float As[BK][68];  // pad 68: float4-aligned rows, reduced store conflicts
    __shared__ float Bs[BK][68];
    int bm = blockIdx.y * 64, bn = blockIdx.x * 64;
    int t  = threadIdx.x;
    int tx = t & 15, ty = t >> 4;
    int lm = t >> 3;         // 0..31
    int lc = (t & 7) * 4;    // k offset within tile: 0,4,...,28

    float acc[4][4];
    #pragma unroll
    for (int i = 0; i < 4; i++)
        #pragma unroll
        for (int j = 0; j < 4; j++) acc[i][j] = 0.f;

    for (int k0 = 0; k0 < HH; k0 += BK) {
        #pragma unroll
        for (int r = 0; r < 2; r++) {
            int ra = bm + lm + r * 32;
            float4 a4 = *reinterpret_cast<const float4*>(A + (size_t)ra * HH + k0 + lc);
            As[lc + 0][lm + r*32] = a4.x;
            As[lc + 1][lm + r*32] = a4.y;
            As[lc + 2][lm + r*32] = a4.z;
            As[lc + 3][lm + r*32] = a4.w;
            int rb = bn + lm + r * 32;
            float4 b4 = *reinterpret_cast<const float4*>(W + (size_t)rb * HH + k0 + lc);
            Bs[lc + 0][lm + r*32] = b4.x;
            Bs[lc + 1][lm + r*32] = b4.y;
            Bs[lc + 2][lm + r*32] = b4.z;
            Bs[lc + 3][lm + r*32] = b4.w;
        }
        __syncthreads();
        #pragma unroll 8
        for (int k = 0; k < BK; k++) {
            float4 av = *reinterpret_cast<float4*>(&As[k][ty * 4]);
            float4 bv = *reinterpret_cast<float4*>(&Bs[k][tx * 4]);
            acc[0][0] = fmaf(av.x, bv.x, acc[0][0]);
            acc[0][1] = fmaf(av.x, bv.y, acc[0][1]);
            acc[0][2] = fmaf(av.x, bv.z, acc[0][2]);
            acc[0][3] = fmaf(av.x, bv.w, acc[0][3]);
            acc[1][0] = fmaf(av.y, bv.x, acc[1][0]);
            acc[1][1] = fmaf(av.y, bv.y, acc[1][1]);
            acc[1][2] = fmaf(av.y, bv.z, acc[1][2]);
            acc[1][3] = fmaf(av.y, bv.w, acc[1][3]);
            acc[2][0] = fmaf(av.z, bv.x, acc[2][0]);
            acc[2][1] = fmaf(av.z, bv.y, acc[2][1]);
            acc[2][2] = fmaf(av.z, bv.z, acc[2][2]);
            acc[2][3] = fmaf(av.z, bv.w, acc[2][3]);
            acc[3][0] = fmaf(av.w, bv.x, acc[3][0]);
            acc[3][1] = fmaf(av.w, bv.y, acc[3][1]);
            acc[3][2] = fmaf(av.w, bv.z, acc[3][2]);
            acc[3][3] = fmaf(av.w, bv.w, acc[3][3]);
        }
        __syncthreads();
    }

    #pragma unroll
    for (int i = 0; i < 4; i++) {
        int row = bm + ty * 4 + i;
        int col = bn + tx * 4;
        float4 o;
        o.x = acc[i][0]; o.y = acc[i][1]; o.z = acc[i][2]; o.w = acc[i][3];
        if (EPI) {
            float4 bb = *reinterpret_cast<const float4*>(bias + col);
            float4 rr = *reinterpret_cast<const float4*>(resid + (size_t)row * HH + col);
            o.x += bb.x + rr.x; o.y += bb.y + rr.y;
            o.z += bb.z + rr.z; o.w += bb.w + rr.w;
        }
        *reinterpret_cast<float4*>(C + (size_t)row * HH + col) = o;
    }
}

// ---------------------------------------------------------------------------
// Flash attention fp32: 1 thread = 1 query row. BQ=128 rows/block, BK=32 keys/tile.
// q, O accumulator in registers (float4[16]); K/V tiles in smem (broadcast reads);
// per-thread score stash in padded smem (stride 33 -> conflict free).
// ---------------------------------------------------------------------------
__global__ __launch_bounds__(128, 2) void attn_kernel() {
    const int BQ = 128, BK = 32;
    int qt = blockIdx.x, h = blockIdx.y, b = blockIdx.z;
    int t = threadIdx.x;

    __shared__ float4 Ks[BK * 16];     // 32 rows x 64 floats
    __shared__ float4 Vs[BK * 16];
    __shared__ float  Scr[BQ * 33];    // per-thread 32 scores, stride 33

    int qrow = qt * BQ + t;
    const float* qptr = g_q + ((size_t)(b * SS + qrow)) * HH + h * HDD;
    float4 q[16];
    #pragma unroll
    for (int i = 0; i < 16; i++) q[i] = *reinterpret_cast<const float4*>(qptr + i * 4);

    float4 acc[16];
    #pragma unroll
    for (int i = 0; i < 16; i++) acc[i] = make_float4(0.f, 0.f, 0.f, 0.f);
    float mrun = -1e30f, lrun = 0.f;
    const float scale = 0.125f;  // 1/sqrt(64)

    const float* Kb = g_k + ((size_t)(b * SS)) * HH + h * HDD;
    const float* Vb = g_v + ((size_t)(b * SS)) * HH + h * HDD;

    for (int k0 = 0; k0 < SS; k0 += BK) {
        #pragma unroll
        for (int i = 0; i < 4; i++) {
            int f = t + i * 128;            // 0..511
            int r = f >> 4, c = f & 15;
            Ks[f] = *reinterpret_cast<const float4*>(Kb + (size_t)(k0 + r) * HH + c * 4);
            Vs[f] = *reinterpret_cast<const float4*>(Vb + (size_t)(k0 + r) * HH + c * 4);
        }
        __syncthreads();

        float tmax = -1e30f;
        #pragma unroll 4
        for (int j = 0; j < BK; j++) {
            float d0 = 0.f, d1 = 0.f, d2 = 0.f, d3 = 0.f;
            #pragma unroll
            for (int v = 0; v < 16; v += 4) {
                float4 ka = Ks[j * 16 + v + 0];
                float4 kb = Ks[j * 16 + v + 1];
                float4 kc = Ks[j * 16 + v + 2];
                float4 kd = Ks[j * 16 + v + 3];
                d0 += q[v+0].x*ka.x + q[v+0].y*ka.y + q[v+0].z*ka.z + q[v+0].w*ka.w;
                d1 += q[v+1].x*kb.x + q[v+1].y*kb.y + q[v+1].z*kb.z + q[v+1].w*kb.w;
                d2 += q[v+2].x*kc.x + q[v+2].y*kc.y + q[v+2].z*kc.z + q[v+2].w*kc.w;
                d3 += q[v+3].x*kd.x + q[v+3].y*kd.y + q[v+3].z*kd.z + q[v+3].w*kd.w;
            }
            float sv = (d0 + d1 + d2 + d3) * scale;
            Scr[t * 33 + j] = sv;
            tmax = fmaxf(tmax, sv);
        }

        float mnew = fmaxf(mrun, tmax);
        float corr = __expf(mrun - mnew);
        lrun *= corr;
        #pragma unroll
        for (int i = 0; i < 16; i++) {
            acc[i].x *= corr; acc[i].y *= corr; acc[i].z *= corr; acc[i].w *= corr;
        }

        #pragma unroll 4
        for (int j = 0; j < BK; j++) {
            float e = __expf(Scr[t * 33 + j] - mnew);
            lrun += e;
            #pragma unroll
            for (int v = 0; v < 16; v++) {
                float4 vv = Vs[j * 16 + v];
                acc[v].x = fmaf(e, vv.x, acc[v].x);
                acc[v].y = fmaf(e, vv.y, acc[v].y);
                acc[v].z = fmaf(e, vv.z, acc[v].z);
                acc[v].w = fmaf(e, vv.w, acc[v].w);
            }
        }
        mrun = mnew;
        __syncthreads();
    }

    float inv = 1.0f / lrun;
    float* op = g_ao + ((size_t)(b * SS + qrow)) * HH + h * HDD;
    #pragma unroll
    for (int i = 0; i < 16; i++) {
        float4 o = acc[i];
        o.x *= inv; o.y *= inv; o.z *= inv; o.w *= inv;
        *reinterpret_cast<float4*>(op + i * 4) = o;
    }
}

// ---------------------------------------------------------------------------
extern "C" void kernel_launch(void* const* d_in, const int* in_sizes, int n_in,
                              void* d_out, int out_size) {
    const float* x     = (const float*)d_in[0];
    const float* Wq    = (const float*)d_in[1];
    const float* Wk    = (const float*)d_in[2];
    const float* Wv    = (const float*)d_in[3];
    const float* Wo    = (const float*)d_in[4];
    const float* bo    = (const float*)d_in[5];
    const float* gamma = (const float*)d_in[6];
    const float* beta  = (const float*)d_in[7];
    float* out = (float*)d_out;

    float *p_xn, *p_q, *p_k, *p_v, *p_ao;
    cudaGetSymbolAddress((void**)&p_xn, g_xn);
    cudaGetSymbolAddress((void**)&p_q,  g_q);
    cudaGetSymbolAddress((void**)&p_k,  g_k);
    cudaGetSymbolAddress((void**)&p_v,  g_v);
    cudaGetSymbolAddress((void**)&p_ao, g_ao);

    // 1. LayerNorm -> g_xn
    ln_kernel<<<MM, 256>>>(x, gamma, beta);

    // 2-4. QKV projections
    dim3 ggrid(HH / 64, MM / 64);
    gemm_nt<false><<<ggrid, 256>>>(p_xn, Wq, p_q, nullptr, nullptr);
    gemm_nt<false><<<ggrid, 256>>>(p_xn, Wk, p_k, nullptr, nullptr);
    gemm_nt<false><<<ggrid, 256>>>(p_xn, Wv, p_v, nullptr, nullptr);

    // 5. attention -> g_ao  (layout [B,S,H] with head-contiguous HD slices)
    dim3 agrid(SS / 128, NHH, BB);
    attn_kernel<<<agrid, 128>>>();

    // 6. output projection + bias + residual -> d_out
    gemm_nt<true><<<ggrid, 256>>>(p_ao, Wo, out, bo, x);
}

// round 5
// speedup vs baseline: 1.0874x; 1.0874x over previous
#include <cuda_runtime.h>

#define BB 2
#define SS 2048
#define HH 1024
#define NHH 16
#define HDD 64
#define MM (BB*SS)   // 4096
#define LN_EPS 1e-5f

// Scratch (allocation-free rule: __device__ globals)
__device__ float g_xn[MM*HH];
__device__ float g_q [MM*HH];
__device__ float g_k [MM*HH];
__device__ float g_v [MM*HH];
__device__ float g_ao[MM*HH];

// ---------------------------------------------------------------------------
// LayerNorm: one block per row, 256 threads, float4
// ---------------------------------------------------------------------------
__global__ __launch_bounds__(256) void ln_kernel(const float* __restrict__ x,
                                                 const float* __restrict__ gamma,
                                                 const float* __restrict__ beta) {
    int row = blockIdx.x;
    int t = threadIdx.x;
    const float4* xr = reinterpret_cast<const float4*>(x + (size_t)row * HH);
    float4 a = xr[t];
    float s  = a.x + a.y + a.z + a.w;
    float sq = a.x*a.x + a.y*a.y + a.z*a.z + a.w*a.w;
    #pragma unroll
    for (int o = 16; o > 0; o >>= 1) {
        s  += __shfl_xor_sync(0xffffffff, s,  o);
        sq += __shfl_xor_sync(0xffffffff, sq, o);
    }
    __shared__ float red0[8], red1[8];
    int wid = t >> 5, lid = t & 31;
    if (lid == 0) { red0[wid] = s; red1[wid] = sq; }
    __syncthreads();
    float fs = 0.f, fq = 0.f;
    #pragma unroll
    for (int i = 0; i < 8; i++) { fs += red0[i]; fq += red1[i]; }
    float mu   = fs * (1.0f / HH);
    float var  = fq * (1.0f / HH) - mu * mu;
    float rstd = rsqrtf(var + LN_EPS);
    float4 gg = reinterpret_cast<const float4*>(gamma)[t];
    float4 bb = reinterpret_cast<const float4*>(beta )[t];
    float4 o;
    o.x = (a.x - mu) * rstd * gg.x + bb.x;
    o.y = (a.y - mu) * rstd * gg.y + bb.y;
    o.z = (a.z - mu) * rstd * gg.z + bb.z;
    o.w = (a.w - mu) * rstd * gg.w + bb.w;
    reinterpret_cast<float4*>(g_xn + (size_t)row * HH)[t] = o;
}

// ---------------------------------------------------------------------------
// GEMM NT: C[m][n] = sum_k A[m][k] * W[n][k]   (A: MMxHH, W: HHxHH row-major)
// 128x128 block tile, BK=16, 256 threads, 8x8 per thread (2x2 of 4x4, float4).
// Smem staged k-major (transposed), pad 132 floats/row.
// EPI: add bias[n] + resid[m][n] (for output projection).
// ---------------------------------------------------------------------------
template<bool EPI>
__global__ __launch_bounds__(256, 2) void gemm_nt(const float* __restrict__ A,
                                                  const float* __restrict__ W,
                                                  float* __restrict__ C,
                                                  const float* __restrict__ bias,
                                                  const float* __restrict__ resid) {
    const int BK = 16;
    __shared__ float As[BK][132];
    __shared__ float Bs[BK][132];
    int bm = blockIdx.y * 128, bn = blockIdx.x * 128;
    int t  = threadIdx.x;
    int txi = t & 15, tyi = t >> 4;

    float acc[8][8];
    #pragma unroll
    for (int i = 0; i < 8; i++)
        #pragma unroll
        for (int j = 0; j < 8; j++) acc[i][j] = 0.f;

    for (int k0 = 0; k0 < HH; k0 += BK) {
        // Stage 128x16 tiles of A and W, transposed to k-major
        #pragma unroll
        for (int r = 0; r < 2; r++) {
            int idx = t + r * 256;           // 0..511
            int row = idx >> 2;              // 0..127
            int c4  = (idx & 3) * 4;         // 0,4,8,12
            float4 a4 = *reinterpret_cast<const float4*>(A + (size_t)(bm + row) * HH + k0 + c4);
            As[c4+0][row] = a4.x; As[c4+1][row] = a4.y;
            As[c4+2][row] = a4.z; As[c4+3][row] = a4.w;
            float4 b4 = *reinterpret_cast<const float4*>(W + (size_t)(bn + row) * HH + k0 + c4);
            Bs[c4+0][row] = b4.x; Bs[c4+1][row] = b4.y;
            Bs[c4+2][row] = b4.z; Bs[c4+3][row] = b4.w;
        }
        __syncthreads();

        #pragma unroll
        for (int k = 0; k < BK; k++) {
            float4 a0 = *reinterpret_cast<float4*>(&As[k][tyi * 4]);
            float4 a1 = *reinterpret_cast<float4*>(&As[k][64 + tyi * 4]);
            float4 b0 = *reinterpret_cast<float4*>(&Bs[k][txi * 4]);
            float4 b1 = *reinterpret_cast<float4*>(&Bs[k][64 + txi * 4]);
            float av[8] = {a0.x, a0.y, a0.z, a0.w, a1.x, a1.y, a1.z, a1.w};
            float bv[8] = {b0.x, b0.y, b0.z, b0.w, b1.x, b1.y, b1.z, b1.w};
            #pragma unroll
            for (int i = 0; i < 8; i++)
                #pragma unroll
                for (int j = 0; j < 8; j++)
                    acc[i][j] = fmaf(av[i], bv[j], acc[i][j]);
        }
        __syncthreads();
    }

    // Epilogue: 2x2 blocks of 4x4, float4 stores
    #pragma unroll
    for (int ri = 0; ri < 2; ri++) {
        #pragma unroll
        for (int i = 0; i < 4; i++) {
            int row = bm + ri * 64 + tyi * 4 + i;
            #pragma unroll
            for (int rj = 0; rj < 2; rj++) {
                int col = bn + rj * 64 + txi * 4;
                float4 o;
                o.x = acc[ri*4+i][rj*4+0];
                o.y = acc[ri*4+i][rj*4+1];
                o.z = acc[ri*4+i][rj*4+2];
                o.w = acc[ri*4+i][rj*4+3];
                if (EPI) {
                    float4 bb = *reinterpret_cast<const float4*>(bias + col);
                    float4 rr = *reinterpret_cast<const float4*>(resid + (size_t)row * HH + col);
                    o.x += bb.x + rr.x; o.y += bb.y + rr.y;
                    o.z += bb.z + rr.z; o.w += bb.w + rr.w;
                }
                *reinterpret_cast<float4*>(C + (size_t)row * HH + col) = o;
            }
        }
    }
}

// ---------------------------------------------------------------------------
// Flash attention fp32: 1 thread = 1 query row. BQ=128 rows/block, BK=32 keys/tile.
// q, O accumulator in registers (float4[16]); K/V tiles in smem (broadcast reads);
// per-thread score stash in padded smem (stride 33 -> conflict free).
// ---------------------------------------------------------------------------
__global__ __launch_bounds__(128, 2) void attn_kernel() {
    const int BQ = 128, BK = 32;
    int qt = blockIdx.x, h = blockIdx.y, b = blockIdx.z;
    int t = threadIdx.x;

    __shared__ float4 Ks[BK * 16];     // 32 rows x 64 floats
    __shared__ float4 Vs[BK * 16];
    __shared__ float  Scr[BQ * 33];    // per-thread 32 scores, stride 33

    int qrow = qt * BQ + t;
    const float* qptr = g_q + ((size_t)(b * SS + qrow)) * HH + h * HDD;
    float4 q[16];
    #pragma unroll
    for (int i = 0; i < 16; i++) q[i] = *reinterpret_cast<const float4*>(qptr + i * 4);

    float4 acc[16];
    #pragma unroll
    for (int i = 0; i < 16; i++) acc[i] = make_float4(0.f, 0.f, 0.f, 0.f);
    float mrun = -1e30f, lrun = 0.f;
    const float scale = 0.125f;  // 1/sqrt(64)

    const float* Kb = g_k + ((size_t)(b * SS)) * HH + h * HDD;
    const float* Vb = g_v + ((size_t)(b * SS)) * HH + h * HDD;

    for (int k0 = 0; k0 < SS; k0 += BK) {
        #pragma unroll
        for (int i = 0; i < 4; i++) {
            int f = t + i * 128;            // 0..511
            int r = f >> 4, c = f & 15;
            Ks[f] = *reinterpret_cast<const float4*>(Kb + (size_t)(k0 + r) * HH + c * 4);
            Vs[f] = *reinterpret_cast<const float4*>(Vb + (size_t)(k0 + r) * HH + c * 4);
        }
        __syncthreads();

        float tmax = -1e30f;
        #pragma unroll 4
        for (int j = 0; j < BK; j++) {
            float d0 = 0.f, d1 = 0.f, d2 = 0.f, d3 = 0.f;
            #pragma unroll
            for (int v = 0; v < 16; v += 4) {
                float4 ka = Ks[j * 16 + v + 0];
                float4 kb = Ks[j * 16 + v + 1];
                float4 kc = Ks[j * 16 + v + 2];
                float4 kd = Ks[j * 16 + v + 3];
                d0 += q[v+0].x*ka.x + q[v+0].y*ka.y + q[v+0].z*ka.z + q[v+0].w*ka.w;
                d1 += q[v+1].x*kb.x + q[v+1].y*kb.y + q[v+1].z*kb.z + q[v+1].w*kb.w;
                d2 += q[v+2].x*kc.x + q[v+2].y*kc.y + q[v+2].z*kc.z + q[v+2].w*kc.w;
                d3 += q[v+3].x*kd.x + q[v+3].y*kd.y + q[v+3].z*kd.z + q[v+3].w*kd.w;
            }
            float sv = (d0 + d1 + d2 + d3) * scale;
            Scr[t * 33 + j] = sv;
            tmax = fmaxf(tmax, sv);
        }

        float mnew = fmaxf(mrun, tmax);
        float corr = __expf(mrun - mnew);
        lrun *= corr;
        #pragma unroll
        for (int i = 0; i < 16; i++) {
            acc[i].x *= corr; acc[i].y *= corr; acc[i].z *= corr; acc[i].w *= corr;
        }

        #pragma unroll 4
        for (int j = 0; j < BK; j++) {
            float e = __expf(Scr[t * 33 + j] - mnew);
            lrun += e;
            #pragma unroll
            for (int v = 0; v < 16; v++) {
                float4 vv = Vs[j * 16 + v];
                acc[v].x = fmaf(e, vv.x, acc[v].x);
                acc[v].y = fmaf(e, vv.y, acc[v].y);
                acc[v].z = fmaf(e, vv.z, acc[v].z);
                acc[v].w = fmaf(e, vv.w, acc[v].w);
            }
        }
        mrun = mnew;
        __syncthreads();
    }

    float inv = 1.0f / lrun;
    float* op = g_ao + ((size_t)(b * SS + qrow)) * HH + h * HDD;
    #pragma unroll
    for (int i = 0; i < 16; i++) {
        float4 o = acc[i];
        o.x *= inv; o.y *= inv; o.z *= inv; o.w *= inv;
        *reinterpret_cast<float4*>(op + i * 4) = o;
    }
}

// ---------------------------------------------------------------------------
extern "C" void kernel_launch(void* const* d_in, const int* in_sizes, int n_in,
                              void* d_out, int out_size) {
    const float* x     = (const float*)d_in[0];
    const float* Wq    = (const float*)d_in[1];
    const float* Wk    = (const float*)d_in[2];
    const float* Wv    = (const float*)d_in[3];
    const float* Wo    = (const float*)d_in[4];
    const float* bo    = (const float*)d_in[5];
    const float* gamma = (const float*)d_in[6];
    const float* beta  = (const float*)d_in[7];
    float* out = (float*)d_out;

    float *p_xn, *p_q, *p_k, *p_v, *p_ao;
    cudaGetSymbolAddress((void**)&p_xn, g_xn);
    cudaGetSymbolAddress((void**)&p_q,  g_q);
    cudaGetSymbolAddress((void**)&p_k,  g_k);
    cudaGetSymbolAddress((void**)&p_v,  g_v);
    cudaGetSymbolAddress((void**)&p_ao, g_ao);

    // 1. LayerNorm -> g_xn
    ln_kernel<<<MM, 256>>>(x, gamma, beta);

    // 2-4. QKV projections
    dim3 ggrid(HH / 128, MM / 128);
    gemm_nt<false><<<ggrid, 256>>>(p_xn, Wq, p_q, nullptr, nullptr);
    gemm_nt<false><<<ggrid, 256>>>(p_xn, Wk, p_k, nullptr, nullptr);
    gemm_nt<false><<<ggrid, 256>>>(p_xn, Wv, p_v, nullptr, nullptr);

    // 5. attention -> g_ao  (layout [B,S,H] with head-contiguous HD slices)
    dim3 agrid(SS / 128, NHH, BB);
    attn_kernel<<<agrid, 128>>>();

    // 6. output projection + bias + residual -> d_out
    gemm_nt<true><<<ggrid, 256>>>(p_ao, Wo, out, bo, x);
}